// round 3
// baseline (speedup 1.0000x reference)
#include <cuda_runtime.h>
#include <cstdint>

#define B_DIM 512
#define F_DIM 784
#define R_DIM 512
#define C_DIM 16
#define D_DIM 49
#define HALF_LOG_2PI 0.9189385332046727f

// Scratch (allocation-free rule: __device__ globals)
__device__ float g_A2[R_DIM * D_DIM * C_DIM * 2];   // [r][d][c] dup f32x2: -0.5/scale^2
__device__ float g_B2[R_DIM * D_DIM * C_DIM * 2];   // [r][d][c] dup f32x2: loc/scale^2
__device__ float g_base[R_DIM * C_DIM];             // [r][c]
__device__ float g_xT[F_DIM * B_DIM];               // [f][b] (1.6MB, L2-resident)

// ---------------------------------------------------------------------------
// packed f32x2 FMA (Blackwell FFMA2 — only reachable via PTX)
// ---------------------------------------------------------------------------
__device__ __forceinline__ unsigned long long fma2(unsigned long long a,
                                                   unsigned long long b,
                                                   unsigned long long c) {
    unsigned long long d;
    asm("fma.rn.f32x2 %0, %1, %2, %3;" : "=l"(d) : "l"(a), "l"(b), "l"(c));
    return d;
}
__device__ __forceinline__ void unpack2(unsigned long long v, float& lo, float& hi) {
    unsigned int l, h;
    asm("mov.b64 {%0, %1}, %2;" : "=r"(l), "=r"(h) : "l"(v));
    lo = __uint_as_float(l);
    hi = __uint_as_float(h);
}
__device__ __forceinline__ uint32_t smem_u32(const void* p) {
    uint32_t a;
    asm("{ .reg .u64 t; cvta.to.shared.u64 t, %1; cvt.u32.u64 %0, t; }" : "=r"(a) : "l"(p));
    return a;
}
__device__ __forceinline__ void cp_async16(uint32_t dst, const void* src) {
    asm volatile("cp.async.cg.shared.global [%0], [%1], 16;" :: "r"(dst), "l"(src));
}

// ---------------------------------------------------------------------------
// Kernel 1: coefficients + base. Coalesced loads via smem staging.
// ---------------------------------------------------------------------------
__global__ void __launch_bounds__(256) prep_kernel(const float* __restrict__ loc,
                                                   const float* __restrict__ scale) {
    int r = blockIdx.x;
    int t = threadIdx.x;
    __shared__ float sloc[784];
    __shared__ float ssc[784];
    __shared__ float s_contrib[C_DIM * D_DIM];   // [c][d]

    #pragma unroll
    for (int i = t; i < 784; i += 256) {
        sloc[i] = loc[r * 784 + i];
        ssc[i]  = scale[r * 784 + i];
    }
    __syncthreads();

    for (int idx = t; idx < 784; idx += 256) {
        int d = idx >> 4;          // idx = d*16 + c
        int c = idx & 15;
        int sl = c * D_DIM + d;    // source layout [c][d]
        float lc = sloc[sl];
        float sc = ssc[sl];
        float A, Bv, contrib;
        if (sc > 0.0f) {
            float inv = 1.0f / sc;
            float w = inv * inv;
            A = -0.5f * w;
            Bv = w * lc;
            contrib = -0.5f * w * lc * lc - __logf(sc) - HALF_LOG_2PI;
        } else {
            A = 0.0f; Bv = 0.0f; contrib = 0.0f;   // reference zeroes NaN logp
        }
        reinterpret_cast<float2*>(g_A2)[r * 784 + idx] = make_float2(A, A);
        reinterpret_cast<float2*>(g_B2)[r * 784 + idx] = make_float2(Bv, Bv);
        s_contrib[sl] = contrib;
    }
    __syncthreads();
    if (t < C_DIM) {
        float s = 0.0f;
        #pragma unroll
        for (int d = 0; d < D_DIM; ++d) s += s_contrib[t * D_DIM + d];
        g_base[r * C_DIM + t] = s;
    }
}

// ---------------------------------------------------------------------------
// Kernel 2: transpose x[b][f] -> xT[f][b].
// ---------------------------------------------------------------------------
__global__ void __launch_bounds__(256) transpose_kernel(const float* __restrict__ x) {
    __shared__ float tile[32][33];
    int fx = blockIdx.x * 32 + threadIdx.x;
    #pragma unroll
    for (int k = 0; k < 32; k += 8) {
        int b = blockIdx.y * 32 + threadIdx.y + k;
        if (fx < F_DIM) tile[threadIdx.y + k][threadIdx.x] = x[b * F_DIM + fx];
    }
    __syncthreads();
    int b_out = blockIdx.y * 32 + threadIdx.x;
    #pragma unroll
    for (int k = 0; k < 32; k += 8) {
        int f = blockIdx.x * 32 + threadIdx.y + k;
        if (f < F_DIM) g_xT[f * B_DIM + b_out] = tile[threadIdx.x][threadIdx.y + k];
    }
}

// ---------------------------------------------------------------------------
// Kernel 3: main. Block = one r, full B=512. 128 threads, thread tile
// 16b x 4c (8 f32x2 b-pairs x 4 c). Per d: 8 LDS.128 + 64 FFMA2 (8:1).
// x gathered from L2-resident xT via cp.async, 7x7 double buffer.
// x smem layout: 32 segments of 16 floats padded to 20 -> the 8 unique
// lane addresses per LDS tile banks 0..31 exactly (conflict-free).
// ---------------------------------------------------------------------------
#define XROW 640            // 32 segments * 20 floats
#define DCHUNK 7
#define NCHUNK 7

__global__ void __launch_bounds__(128, 4) main_kernel(const int* __restrict__ mask,
                                                      float* __restrict__ out) {
    int r   = blockIdx.x;
    int tid = threadIdx.x;

    __shared__ __align__(16) float sA2[D_DIM * 32];       // [d][c dup pairs]
    __shared__ __align__(16) float sB2[D_DIM * 32];
    __shared__ __align__(16) float xs[2][DCHUNK * XROW];
    __shared__ int smask[D_DIM];

    if (tid < D_DIM) smask[tid] = mask[r * D_DIM + tid];
    {
        const float4* Ag = reinterpret_cast<const float4*>(g_A2 + r * (D_DIM * 32));
        const float4* Bg = reinterpret_cast<const float4*>(g_B2 + r * (D_DIM * 32));
        float4* As4 = reinterpret_cast<float4*>(sA2);
        float4* Bs4 = reinterpret_cast<float4*>(sB2);
        #pragma unroll
        for (int i = 0; i < 4; ++i) {
            int idx = tid + i * 128;
            if (idx < 392) { As4[idx] = Ag[idx]; Bs4[idx] = Bg[idx]; }
        }
    }
    __syncthreads();    // smask + coeffs ready

    // per-thread gather addressing: for chunk step s (=local d), q = tid (float4 idx)
    const float* xTp = g_xT;
    int q = tid;                                   // 0..127 float4 per d-row
    uint32_t dst_off = (uint32_t)((q >> 2) * 20 + (q & 3) * 4) * 4u;  // bytes in row
    uint32_t xs_base[2] = { smem_u32(&xs[0][0]), smem_u32(&xs[1][0]) };

    // prefetch chunks 0 and 1
    #pragma unroll
    for (int s = 0; s < DCHUNK; ++s)
        cp_async16(xs_base[0] + (uint32_t)(s * XROW) * 4u + dst_off,
                   xTp + (size_t)smask[s] * B_DIM + q * 4);
    asm volatile("cp.async.commit_group;");
    #pragma unroll
    for (int s = 0; s < DCHUNK; ++s)
        cp_async16(xs_base[1] + (uint32_t)(s * XROW) * 4u + dst_off,
                   xTp + (size_t)smask[DCHUNK + s] * B_DIM + q * 4);
    asm volatile("cp.async.commit_group;");

    int g = tid >> 2;    // 0..31 -> b segment (16 b's)
    int h = tid & 3;     // 0..3  -> c = 4h + 0..3

    unsigned long long acc[8][4];
    #pragma unroll
    for (int p = 0; p < 8; ++p)
        #pragma unroll
        for (int j = 0; j < 4; ++j) acc[p][j] = 0ull;

    for (int k = 0; k < NCHUNK; ++k) {
        if (k < NCHUNK - 1) asm volatile("cp.async.wait_group 1;");
        else                asm volatile("cp.async.wait_group 0;");
        __syncthreads();                     // buf[k&1] visible to all

        const float* xb = &xs[k & 1][g * 20];
        const float* Ab = sA2 + k * (DCHUNK * 32) + h * 8;
        const float* Bb = sB2 + k * (DCHUNK * 32) + h * 8;

        #pragma unroll
        for (int dd = 0; dd < DCHUNK; ++dd) {
            ulonglong2 xa = *reinterpret_cast<const ulonglong2*>(xb + dd * XROW);
            ulonglong2 xc = *reinterpret_cast<const ulonglong2*>(xb + dd * XROW + 4);
            ulonglong2 xe = *reinterpret_cast<const ulonglong2*>(xb + dd * XROW + 8);
            ulonglong2 xg = *reinterpret_cast<const ulonglong2*>(xb + dd * XROW + 12);
            ulonglong2 aa = *reinterpret_cast<const ulonglong2*>(Ab + dd * 32);
            ulonglong2 ac = *reinterpret_cast<const ulonglong2*>(Ab + dd * 32 + 4);
            ulonglong2 ba = *reinterpret_cast<const ulonglong2*>(Bb + dd * 32);
            ulonglong2 bc = *reinterpret_cast<const ulonglong2*>(Bb + dd * 32 + 4);
            unsigned long long x2[8] = {xa.x, xa.y, xc.x, xc.y, xe.x, xe.y, xg.x, xg.y};
            unsigned long long a2[4] = {aa.x, aa.y, ac.x, ac.y};
            unsigned long long b2[4] = {ba.x, ba.y, bc.x, bc.y};
            #pragma unroll
            for (int j = 0; j < 4; ++j)
                #pragma unroll
                for (int p = 0; p < 8; ++p) {
                    unsigned long long t = fma2(a2[j], x2[p], b2[j]);
                    acc[p][j] = fma2(x2[p], t, acc[p][j]);
                }
        }
        __syncthreads();                     // done reading buf[k&1]

        if (k + 2 < NCHUNK) {                // refill buf[k&1] with chunk k+2
            int d0 = (k + 2) * DCHUNK;
            #pragma unroll
            for (int s = 0; s < DCHUNK; ++s)
                cp_async16(xs_base[k & 1] + (uint32_t)(s * XROW) * 4u + dst_off,
                           xTp + (size_t)smask[d0 + s] * B_DIM + q * 4);
            asm volatile("cp.async.commit_group;");
        }
    }

    // epilogue: unpack pairs, add base, store
    float4 bb4 = *reinterpret_cast<const float4*>(g_base + r * C_DIM + h * 4);
    float bb[4] = {bb4.x, bb4.y, bb4.z, bb4.w};
    int b0 = g * 16;

    #pragma unroll
    for (int p = 0; p < 8; ++p) {
        float lo[4], hi[4];
        #pragma unroll
        for (int j = 0; j < 4; ++j) unpack2(acc[p][j], lo[j], hi[j]);
        float4 o0, o1;
        o0.x = lo[0] + bb[0]; o0.y = lo[1] + bb[1]; o0.z = lo[2] + bb[2]; o0.w = lo[3] + bb[3];
        o1.x = hi[0] + bb[0]; o1.y = hi[1] + bb[1]; o1.z = hi[2] + bb[2]; o1.w = hi[3] + bb[3];
        size_t row = (size_t)(b0 + 2 * p) * (R_DIM * C_DIM) + r * C_DIM + h * 4;
        *reinterpret_cast<float4*>(out + row) = o0;
        *reinterpret_cast<float4*>(out + row + (R_DIM * C_DIM)) = o1;
    }
}

// ---------------------------------------------------------------------------
extern "C" void kernel_launch(void* const* d_in, const int* in_sizes, int n_in,
                              void* d_out, int out_size) {
    const float* x     = (const float*)d_in[0];
    const int*   mask  = (const int*)d_in[1];
    const float* loc   = (const float*)d_in[2];
    const float* scale = (const float*)d_in[3];
    float* out = (float*)d_out;

    prep_kernel<<<R_DIM, 256>>>(loc, scale);
    transpose_kernel<<<dim3((F_DIM + 31) / 32, B_DIM / 32), dim3(32, 8)>>>(x);
    main_kernel<<<R_DIM, 128>>>(mask, out);
}

// round 4
// speedup vs baseline: 1.0058x; 1.0058x over previous
#include <cuda_runtime.h>
#include <cstdint>

#define B_DIM 512
#define F_DIM 784
#define R_DIM 512
#define C_DIM 16
#define D_DIM 49
#define HALF_LOG_2PI 0.9189385332046727f

// Scratch (allocation-free rule: __device__ globals)
__device__ float g_A2[R_DIM * D_DIM * C_DIM * 2];   // [r][d][c] dup f32x2: -0.5/scale^2
__device__ float g_B2[R_DIM * D_DIM * C_DIM * 2];   // [r][d][c] dup f32x2: loc/scale^2
__device__ float g_base[R_DIM * C_DIM];             // [r][c]
__device__ float g_xT[F_DIM * B_DIM];               // [f][b] (1.6MB, L2-resident)

// ---------------------------------------------------------------------------
// packed f32x2 FMA (Blackwell FFMA2 — only reachable via PTX)
// ---------------------------------------------------------------------------
__device__ __forceinline__ unsigned long long fma2(unsigned long long a,
                                                   unsigned long long b,
                                                   unsigned long long c) {
    unsigned long long d;
    asm("fma.rn.f32x2 %0, %1, %2, %3;" : "=l"(d) : "l"(a), "l"(b), "l"(c));
    return d;
}
__device__ __forceinline__ void unpack2(unsigned long long v, float& lo, float& hi) {
    unsigned int l, h;
    asm("mov.b64 {%0, %1}, %2;" : "=r"(l), "=r"(h) : "l"(v));
    lo = __uint_as_float(l);
    hi = __uint_as_float(h);
}
__device__ __forceinline__ uint32_t smem_u32(const void* p) {
    uint32_t a;
    asm("{ .reg .u64 t; cvta.to.shared.u64 t, %1; cvt.u32.u64 %0, t; }" : "=r"(a) : "l"(p));
    return a;
}
__device__ __forceinline__ void cp_async16(uint32_t dst, const void* src) {
    asm volatile("cp.async.cg.shared.global [%0], [%1], 16;" :: "r"(dst), "l"(src));
}

// ---------------------------------------------------------------------------
// Kernel 1: coefficients + base. Coalesced loads via smem staging.
// ---------------------------------------------------------------------------
__global__ void __launch_bounds__(256) prep_kernel(const float* __restrict__ loc,
                                                   const float* __restrict__ scale) {
    int r = blockIdx.x;
    int t = threadIdx.x;
    __shared__ float sloc[784];
    __shared__ float ssc[784];
    __shared__ float s_contrib[C_DIM * D_DIM];   // [c][d]

    #pragma unroll
    for (int i = t; i < 784; i += 256) {
        sloc[i] = loc[r * 784 + i];
        ssc[i]  = scale[r * 784 + i];
    }
    __syncthreads();

    for (int idx = t; idx < 784; idx += 256) {
        int d = idx >> 4;          // idx = d*16 + c
        int c = idx & 15;
        int sl = c * D_DIM + d;    // source layout [c][d]
        float lc = sloc[sl];
        float sc = ssc[sl];
        float A, Bv, contrib;
        if (sc > 0.0f) {
            float inv = 1.0f / sc;
            float w = inv * inv;
            A = -0.5f * w;
            Bv = w * lc;
            contrib = -0.5f * w * lc * lc - __logf(sc) - HALF_LOG_2PI;
        } else {
            A = 0.0f; Bv = 0.0f; contrib = 0.0f;   // reference zeroes NaN logp
        }
        reinterpret_cast<float2*>(g_A2)[r * 784 + idx] = make_float2(A, A);
        reinterpret_cast<float2*>(g_B2)[r * 784 + idx] = make_float2(Bv, Bv);
        s_contrib[sl] = contrib;
    }
    __syncthreads();
    if (t < C_DIM) {
        float s = 0.0f;
        #pragma unroll
        for (int d = 0; d < D_DIM; ++d) s += s_contrib[t * D_DIM + d];
        g_base[r * C_DIM + t] = s;
    }
}

// ---------------------------------------------------------------------------
// Kernel 2: transpose x[b][f] -> xT[f][b].
// ---------------------------------------------------------------------------
__global__ void __launch_bounds__(256) transpose_kernel(const float* __restrict__ x) {
    __shared__ float tile[32][33];
    int fx = blockIdx.x * 32 + threadIdx.x;
    #pragma unroll
    for (int k = 0; k < 32; k += 8) {
        int b = blockIdx.y * 32 + threadIdx.y + k;
        if (fx < F_DIM) tile[threadIdx.y + k][threadIdx.x] = x[b * F_DIM + fx];
    }
    __syncthreads();
    int b_out = blockIdx.y * 32 + threadIdx.x;
    #pragma unroll
    for (int k = 0; k < 32; k += 8) {
        int f = blockIdx.x * 32 + threadIdx.y + k;
        if (f < F_DIM) g_xT[f * B_DIM + b_out] = tile[threadIdx.x][threadIdx.y + k];
    }
}

// ---------------------------------------------------------------------------
// Kernel 3: main. Block = one r, full B=512. 128 threads, thread tile
// 16b x 4c (8 f32x2 b-pairs x 4 c). Per d: 8 LDS.128 + 64 FFMA2 (8:1).
// x gathered from L2-resident xT via cp.async, 7x7 double buffer.
// x smem layout: 32 segments of 16 floats padded to 20 -> the 8 unique
// lane addresses per LDS tile banks 0..31 exactly (conflict-free).
// ---------------------------------------------------------------------------
#define XROW 640            // 32 segments * 20 floats
#define DCHUNK 7
#define NCHUNK 7

__global__ void __launch_bounds__(128, 4) main_kernel(const int* __restrict__ mask,
                                                      float* __restrict__ out) {
    int r   = blockIdx.x;
    int tid = threadIdx.x;

    __shared__ __align__(16) float sA2[D_DIM * 32];       // [d][c dup pairs]
    __shared__ __align__(16) float sB2[D_DIM * 32];
    __shared__ __align__(16) float xs[2][DCHUNK * XROW];
    __shared__ int smask[D_DIM];

    if (tid < D_DIM) smask[tid] = mask[r * D_DIM + tid];
    {
        const float4* Ag = reinterpret_cast<const float4*>(g_A2 + r * (D_DIM * 32));
        const float4* Bg = reinterpret_cast<const float4*>(g_B2 + r * (D_DIM * 32));
        float4* As4 = reinterpret_cast<float4*>(sA2);
        float4* Bs4 = reinterpret_cast<float4*>(sB2);
        #pragma unroll
        for (int i = 0; i < 4; ++i) {
            int idx = tid + i * 128;
            if (idx < 392) { As4[idx] = Ag[idx]; Bs4[idx] = Bg[idx]; }
        }
    }
    __syncthreads();    // smask + coeffs ready

    // per-thread gather addressing: for chunk step s (=local d), q = tid (float4 idx)
    const float* xTp = g_xT;
    int q = tid;                                   // 0..127 float4 per d-row
    uint32_t dst_off = (uint32_t)((q >> 2) * 20 + (q & 3) * 4) * 4u;  // bytes in row
    uint32_t xs_base[2] = { smem_u32(&xs[0][0]), smem_u32(&xs[1][0]) };

    // prefetch chunks 0 and 1
    #pragma unroll
    for (int s = 0; s < DCHUNK; ++s)
        cp_async16(xs_base[0] + (uint32_t)(s * XROW) * 4u + dst_off,
                   xTp + (size_t)smask[s] * B_DIM + q * 4);
    asm volatile("cp.async.commit_group;");
    #pragma unroll
    for (int s = 0; s < DCHUNK; ++s)
        cp_async16(xs_base[1] + (uint32_t)(s * XROW) * 4u + dst_off,
                   xTp + (size_t)smask[DCHUNK + s] * B_DIM + q * 4);
    asm volatile("cp.async.commit_group;");

    int g = tid >> 2;    // 0..31 -> b segment (16 b's)
    int h = tid & 3;     // 0..3  -> c = 4h + 0..3

    unsigned long long acc[8][4];
    #pragma unroll
    for (int p = 0; p < 8; ++p)
        #pragma unroll
        for (int j = 0; j < 4; ++j) acc[p][j] = 0ull;

    for (int k = 0; k < NCHUNK; ++k) {
        if (k < NCHUNK - 1) asm volatile("cp.async.wait_group 1;");
        else                asm volatile("cp.async.wait_group 0;");
        __syncthreads();                     // buf[k&1] visible to all

        const float* xb = &xs[k & 1][g * 20];
        const float* Ab = sA2 + k * (DCHUNK * 32) + h * 8;
        const float* Bb = sB2 + k * (DCHUNK * 32) + h * 8;

        #pragma unroll
        for (int dd = 0; dd < DCHUNK; ++dd) {
            ulonglong2 xa = *reinterpret_cast<const ulonglong2*>(xb + dd * XROW);
            ulonglong2 xc = *reinterpret_cast<const ulonglong2*>(xb + dd * XROW + 4);
            ulonglong2 xe = *reinterpret_cast<const ulonglong2*>(xb + dd * XROW + 8);
            ulonglong2 xg = *reinterpret_cast<const ulonglong2*>(xb + dd * XROW + 12);
            ulonglong2 aa = *reinterpret_cast<const ulonglong2*>(Ab + dd * 32);
            ulonglong2 ac = *reinterpret_cast<const ulonglong2*>(Ab + dd * 32 + 4);
            ulonglong2 ba = *reinterpret_cast<const ulonglong2*>(Bb + dd * 32);
            ulonglong2 bc = *reinterpret_cast<const ulonglong2*>(Bb + dd * 32 + 4);
            unsigned long long x2[8] = {xa.x, xa.y, xc.x, xc.y, xe.x, xe.y, xg.x, xg.y};
            unsigned long long a2[4] = {aa.x, aa.y, ac.x, ac.y};
            unsigned long long b2[4] = {ba.x, ba.y, bc.x, bc.y};
            #pragma unroll
            for (int j = 0; j < 4; ++j)
                #pragma unroll
                for (int p = 0; p < 8; ++p) {
                    unsigned long long t = fma2(a2[j], x2[p], b2[j]);
                    acc[p][j] = fma2(x2[p], t, acc[p][j]);
                }
        }
        __syncthreads();                     // done reading buf[k&1]

        if (k + 2 < NCHUNK) {                // refill buf[k&1] with chunk k+2
            int d0 = (k + 2) * DCHUNK;
            #pragma unroll
            for (int s = 0; s < DCHUNK; ++s)
                cp_async16(xs_base[k & 1] + (uint32_t)(s * XROW) * 4u + dst_off,
                           xTp + (size_t)smask[d0 + s] * B_DIM + q * 4);
            asm volatile("cp.async.commit_group;");
        }
    }

    // epilogue: unpack pairs, add base, store
    float4 bb4 = *reinterpret_cast<const float4*>(g_base + r * C_DIM + h * 4);
    float bb[4] = {bb4.x, bb4.y, bb4.z, bb4.w};
    int b0 = g * 16;

    #pragma unroll
    for (int p = 0; p < 8; ++p) {
        float lo[4], hi[4];
        #pragma unroll
        for (int j = 0; j < 4; ++j) unpack2(acc[p][j], lo[j], hi[j]);
        float4 o0, o1;
        o0.x = lo[0] + bb[0]; o0.y = lo[1] + bb[1]; o0.z = lo[2] + bb[2]; o0.w = lo[3] + bb[3];
        o1.x = hi[0] + bb[0]; o1.y = hi[1] + bb[1]; o1.z = hi[2] + bb[2]; o1.w = hi[3] + bb[3];
        size_t row = (size_t)(b0 + 2 * p) * (R_DIM * C_DIM) + r * C_DIM + h * 4;
        *reinterpret_cast<float4*>(out + row) = o0;
        *reinterpret_cast<float4*>(out + row + (R_DIM * C_DIM)) = o1;
    }
}

// ---------------------------------------------------------------------------
extern "C" void kernel_launch(void* const* d_in, const int* in_sizes, int n_in,
                              void* d_out, int out_size) {
    const float* x     = (const float*)d_in[0];
    const int*   mask  = (const int*)d_in[1];
    const float* loc   = (const float*)d_in[2];
    const float* scale = (const float*)d_in[3];
    float* out = (float*)d_out;

    prep_kernel<<<R_DIM, 256>>>(loc, scale);
    transpose_kernel<<<dim3((F_DIM + 31) / 32, B_DIM / 32), dim3(32, 8)>>>(x);
    main_kernel<<<R_DIM, 128>>>(mask, out);
}

// round 5
// speedup vs baseline: 1.0630x; 1.0569x over previous
#include <cuda_runtime.h>
#include <cstdint>

#define B_DIM 512
#define F_DIM 784
#define R_DIM 512
#define C_DIM 16
#define D_DIM 49
#define HALF_LOG_2PI 0.9189385332046727f

// Scratch (allocation-free rule: __device__ global)
__device__ float g_xT[F_DIM * B_DIM];               // [f][b] (1.6MB, L2-resident)

// ---------------------------------------------------------------------------
// packed f32x2 FMA (Blackwell FFMA2 — only reachable via PTX)
// ---------------------------------------------------------------------------
__device__ __forceinline__ unsigned long long fma2(unsigned long long a,
                                                   unsigned long long b,
                                                   unsigned long long c) {
    unsigned long long d;
    asm("fma.rn.f32x2 %0, %1, %2, %3;" : "=l"(d) : "l"(a), "l"(b), "l"(c));
    return d;
}
__device__ __forceinline__ void unpack2(unsigned long long v, float& lo, float& hi) {
    unsigned int l, h;
    asm("mov.b64 {%0, %1}, %2;" : "=r"(l), "=r"(h) : "l"(v));
    lo = __uint_as_float(l);
    hi = __uint_as_float(h);
}
__device__ __forceinline__ uint32_t smem_u32(const void* p) {
    uint32_t a;
    asm("{ .reg .u64 t; cvta.to.shared.u64 t, %1; cvt.u32.u64 %0, t; }" : "=r"(a) : "l"(p));
    return a;
}
__device__ __forceinline__ void cp_async16(uint32_t dst, const void* src) {
    asm volatile("cp.async.cg.shared.global [%0], [%1], 16;" :: "r"(dst), "l"(src));
}

// ---------------------------------------------------------------------------
// Kernel 1: transpose x[b][f] -> xT[f][b].
// ---------------------------------------------------------------------------
__global__ void __launch_bounds__(256) transpose_kernel(const float* __restrict__ x) {
    __shared__ float tile[32][33];
    int fx = blockIdx.x * 32 + threadIdx.x;
    #pragma unroll
    for (int k = 0; k < 32; k += 8) {
        int b = blockIdx.y * 32 + threadIdx.y + k;
        if (fx < F_DIM) tile[threadIdx.y + k][threadIdx.x] = x[b * F_DIM + fx];
    }
    __syncthreads();
    int b_out = blockIdx.y * 32 + threadIdx.x;
    #pragma unroll
    for (int k = 0; k < 32; k += 8) {
        int f = blockIdx.x * 32 + threadIdx.y + k;
        if (f < F_DIM) g_xT[f * B_DIM + b_out] = tile[threadIdx.x][threadIdx.y + k];
    }
}

// ---------------------------------------------------------------------------
// Kernel 2: fused prep + main. Block = one r, full B=512, 128 threads,
// thread tile 16b x 4c (8 f32x2 b-pairs x 4 c). Per d: 8 LDS.128 + 64 FFMA2.
//
// Prep is computed in-block: loc/scale rows staged coalesced into the xs[1]
// buffer (not yet needed — chunk-1 gather is issued after), coefficients
// written straight to sA2/sB2 smem, base reduced with 8-lane shuffles.
// The coeff math overlaps the chunk-0 cp.async gather latency.
//
// x smem layout: 32 segments of 16 floats padded to 20 -> the 8 unique lane
// addresses per LDS.128 tile banks 0..31 exactly (conflict-free).
// ---------------------------------------------------------------------------
#define XROW 640            // 32 segments * 20 floats
#define DCHUNK 7
#define NCHUNK 7

__global__ void __launch_bounds__(128, 4) main_kernel(const float* __restrict__ loc,
                                                      const float* __restrict__ scale,
                                                      const int* __restrict__ mask,
                                                      float* __restrict__ out) {
    int r   = blockIdx.x;
    int tid = threadIdx.x;

    __shared__ __align__(16) float sA2[D_DIM * 32];       // [d][c dup pairs]
    __shared__ __align__(16) float sB2[D_DIM * 32];
    __shared__ __align__(16) float xs[2][DCHUNK * XROW];
    __shared__ int   smask[D_DIM];
    __shared__ float sbase[C_DIM];

    // ---- mask first (gather addresses) ----
    if (tid < D_DIM) smask[tid] = mask[r * D_DIM + tid];
    __syncthreads();

    const float* xTp = g_xT;
    int q = tid;                                   // float4 index within a d-row
    uint32_t dst_off = (uint32_t)((q >> 2) * 20 + (q & 3) * 4) * 4u;  // bytes in row
    uint32_t xs_base[2] = { smem_u32(&xs[0][0]), smem_u32(&xs[1][0]) };

    // ---- chunk 0 gather in flight while we do the coefficient math ----
    #pragma unroll
    for (int s = 0; s < DCHUNK; ++s)
        cp_async16(xs_base[0] + (uint32_t)(s * XROW) * 4u + dst_off,
                   xTp + (size_t)smask[s] * B_DIM + q * 4);
    asm volatile("cp.async.commit_group;");

    // ---- stage loc/scale rows (coalesced) into xs[1] (free right now) ----
    float* sloc     = &xs[1][0];
    float* ssc      = &xs[1][784];
    float* scontrib = &xs[1][1568];     // [c][d]
    for (int i = tid; i < 784; i += 128) {
        sloc[i] = loc[r * 784 + i];
        ssc[i]  = scale[r * 784 + i];
    }
    __syncthreads();

    // ---- coefficients straight into smem tiles ----
    for (int i = tid; i < 784; i += 128) {
        int d = i >> 4;                 // i = d*16 + c
        int c = i & 15;
        int sl = c * D_DIM + d;         // source layout [c][d]
        float lc = sloc[sl];
        float sc = ssc[sl];
        float A, Bv, contrib;
        if (sc > 0.0f) {
            float inv = 1.0f / sc;
            float w = inv * inv;
            A = -0.5f * w;
            Bv = w * lc;
            contrib = -0.5f * w * lc * lc - __logf(sc) - HALF_LOG_2PI;
        } else {
            A = 0.0f; Bv = 0.0f; contrib = 0.0f;   // reference zeroes NaN logp
        }
        sA2[d * 32 + c * 2]     = A;
        sA2[d * 32 + c * 2 + 1] = A;
        sB2[d * 32 + c * 2]     = Bv;
        sB2[d * 32 + c * 2 + 1] = Bv;
        scontrib[sl] = contrib;
    }
    __syncthreads();

    // ---- base[c] reduction: 8 threads per c, shuffle within 8-lane groups ----
    {
        int c  = tid >> 3;          // 0..15
        int l8 = tid & 7;
        float s = 0.0f;
        for (int d = l8; d < D_DIM; d += 8) s += scontrib[c * D_DIM + d];
        s += __shfl_down_sync(0xffffffffu, s, 4, 8);
        s += __shfl_down_sync(0xffffffffu, s, 2, 8);
        s += __shfl_down_sync(0xffffffffu, s, 1, 8);
        if (l8 == 0) sbase[c] = s;
    }
    __syncthreads();    // staging reads done -> xs[1] free for chunk 1

    // ---- chunk 1 gather ----
    #pragma unroll
    for (int s = 0; s < DCHUNK; ++s)
        cp_async16(xs_base[1] + (uint32_t)(s * XROW) * 4u + dst_off,
                   xTp + (size_t)smask[DCHUNK + s] * B_DIM + q * 4);
    asm volatile("cp.async.commit_group;");

    int g = tid >> 2;    // 0..31 -> b segment (16 b's)
    int h = tid & 3;     // 0..3  -> c = 4h + 0..3

    unsigned long long acc[8][4];
    #pragma unroll
    for (int p = 0; p < 8; ++p)
        #pragma unroll
        for (int j = 0; j < 4; ++j) acc[p][j] = 0ull;

    for (int k = 0; k < NCHUNK; ++k) {
        if (k < NCHUNK - 1) asm volatile("cp.async.wait_group 1;");
        else                asm volatile("cp.async.wait_group 0;");
        __syncthreads();                     // buf[k&1] visible to all

        const float* xb = &xs[k & 1][g * 20];
        const float* Ab = sA2 + k * (DCHUNK * 32) + h * 8;
        const float* Bb = sB2 + k * (DCHUNK * 32) + h * 8;

        #pragma unroll
        for (int dd = 0; dd < DCHUNK; ++dd) {
            ulonglong2 xa = *reinterpret_cast<const ulonglong2*>(xb + dd * XROW);
            ulonglong2 xc = *reinterpret_cast<const ulonglong2*>(xb + dd * XROW + 4);
            ulonglong2 xe = *reinterpret_cast<const ulonglong2*>(xb + dd * XROW + 8);
            ulonglong2 xg = *reinterpret_cast<const ulonglong2*>(xb + dd * XROW + 12);
            ulonglong2 aa = *reinterpret_cast<const ulonglong2*>(Ab + dd * 32);
            ulonglong2 ac = *reinterpret_cast<const ulonglong2*>(Ab + dd * 32 + 4);
            ulonglong2 ba = *reinterpret_cast<const ulonglong2*>(Bb + dd * 32);
            ulonglong2 bc = *reinterpret_cast<const ulonglong2*>(Bb + dd * 32 + 4);
            unsigned long long x2[8] = {xa.x, xa.y, xc.x, xc.y, xe.x, xe.y, xg.x, xg.y};
            unsigned long long a2[4] = {aa.x, aa.y, ac.x, ac.y};
            unsigned long long b2[4] = {ba.x, ba.y, bc.x, bc.y};
            #pragma unroll
            for (int j = 0; j < 4; ++j)
                #pragma unroll
                for (int p = 0; p < 8; ++p) {
                    unsigned long long t = fma2(a2[j], x2[p], b2[j]);
                    acc[p][j] = fma2(x2[p], t, acc[p][j]);
                }
        }
        __syncthreads();                     // done reading buf[k&1]

        if (k + 2 < NCHUNK) {                // refill buf[k&1] with chunk k+2
            int d0 = (k + 2) * DCHUNK;
            #pragma unroll
            for (int s = 0; s < DCHUNK; ++s)
                cp_async16(xs_base[k & 1] + (uint32_t)(s * XROW) * 4u + dst_off,
                           xTp + (size_t)smask[d0 + s] * B_DIM + q * 4);
            asm volatile("cp.async.commit_group;");
        }
    }

    // ---- epilogue: unpack pairs, add base, store ----
    float bb[4] = { sbase[h * 4], sbase[h * 4 + 1], sbase[h * 4 + 2], sbase[h * 4 + 3] };
    int b0 = g * 16;

    #pragma unroll
    for (int p = 0; p < 8; ++p) {
        float lo[4], hi[4];
        #pragma unroll
        for (int j = 0; j < 4; ++j) unpack2(acc[p][j], lo[j], hi[j]);
        float4 o0, o1;
        o0.x = lo[0] + bb[0]; o0.y = lo[1] + bb[1]; o0.z = lo[2] + bb[2]; o0.w = lo[3] + bb[3];
        o1.x = hi[0] + bb[0]; o1.y = hi[1] + bb[1]; o1.z = hi[2] + bb[2]; o1.w = hi[3] + bb[3];
        size_t row = (size_t)(b0 + 2 * p) * (R_DIM * C_DIM) + r * C_DIM + h * 4;
        *reinterpret_cast<float4*>(out + row) = o0;
        *reinterpret_cast<float4*>(out + row + (R_DIM * C_DIM)) = o1;
    }
}

// ---------------------------------------------------------------------------
extern "C" void kernel_launch(void* const* d_in, const int* in_sizes, int n_in,
                              void* d_out, int out_size) {
    const float* x     = (const float*)d_in[0];
    const int*   mask  = (const int*)d_in[1];
    const float* loc   = (const float*)d_in[2];
    const float* scale = (const float*)d_in[3];
    float* out = (float*)d_out;

    transpose_kernel<<<dim3((F_DIM + 31) / 32, B_DIM / 32), dim3(32, 8)>>>(x);
    main_kernel<<<R_DIM, 128>>>(loc, scale, mask, out);
}

// round 6
// speedup vs baseline: 1.0728x; 1.0092x over previous
#include <cuda_runtime.h>
#include <cstdint>

#define B_DIM 512
#define F_DIM 784
#define R_DIM 512
#define C_DIM 16
#define D_DIM 49
#define HALF_LOG_2PI 0.9189385332046727f

// Scratch (allocation-free rule: __device__ global)
__device__ float g_xT[F_DIM * B_DIM];               // [f][b] (1.6MB, L2-resident)

// ---------------------------------------------------------------------------
// packed f32x2 FMA (Blackwell FFMA2 — only reachable via PTX)
// ---------------------------------------------------------------------------
__device__ __forceinline__ unsigned long long fma2(unsigned long long a,
                                                   unsigned long long b,
                                                   unsigned long long c) {
    unsigned long long d;
    asm("fma.rn.f32x2 %0, %1, %2, %3;" : "=l"(d) : "l"(a), "l"(b), "l"(c));
    return d;
}
__device__ __forceinline__ void unpack2(unsigned long long v, float& lo, float& hi) {
    unsigned int l, h;
    asm("mov.b64 {%0, %1}, %2;" : "=r"(l), "=r"(h) : "l"(v));
    lo = __uint_as_float(l);
    hi = __uint_as_float(h);
}
__device__ __forceinline__ uint32_t smem_u32(const void* p) {
    uint32_t a;
    asm("{ .reg .u64 t; cvta.to.shared.u64 t, %1; cvt.u32.u64 %0, t; }" : "=r"(a) : "l"(p));
    return a;
}
__device__ __forceinline__ void cp_async16(uint32_t dst, const void* src) {
    asm volatile("cp.async.cg.shared.global [%0], [%1], 16;" :: "r"(dst), "l"(src));
}

// ---------------------------------------------------------------------------
// Kernel 1: transpose x[b][f] -> xT[f][b].
// ---------------------------------------------------------------------------
__global__ void __launch_bounds__(256) transpose_kernel(const float* __restrict__ x) {
    __shared__ float tile[32][33];
    int fx = blockIdx.x * 32 + threadIdx.x;
    #pragma unroll
    for (int k = 0; k < 32; k += 8) {
        int b = blockIdx.y * 32 + threadIdx.y + k;
        if (fx < F_DIM) tile[threadIdx.y + k][threadIdx.x] = x[b * F_DIM + fx];
    }
    __syncthreads();
    int b_out = blockIdx.y * 32 + threadIdx.x;
    #pragma unroll
    for (int k = 0; k < 32; k += 8) {
        int f = blockIdx.x * 32 + threadIdx.y + k;
        if (f < F_DIM) g_xT[f * B_DIM + b_out] = tile[threadIdx.x][threadIdx.y + k];
    }
}

// ---------------------------------------------------------------------------
// Kernel 2: fused prep + main. Block = one r, full B=512, 256 threads,
// thread tile 16b x 2c (8 f32x2 b-pairs x 2 c). Per d: 6 LDS.128 + 32 FFMA2.
// acc = 32 regs/thread -> ~80 total regs -> 8 warps/block, 4 blocks/SM.
//
// Prep computed in-block (overlapping chunk-0 cp.async gather latency);
// loc/scale staged into the not-yet-needed xs[1] buffer.
//
// x smem layout: 32 segments of 16 floats padded to 20. Per LDS.128 a warp
// touches 4 distinct segments -> banks {0-3},{20-23},{8-11},{28-31}: clean.
// ---------------------------------------------------------------------------
#define XROW 640            // 32 segments * 20 floats
#define DCHUNK 7
#define NCHUNK 7

__global__ void __launch_bounds__(256, 4) main_kernel(const float* __restrict__ loc,
                                                      const float* __restrict__ scale,
                                                      const int* __restrict__ mask,
                                                      float* __restrict__ out) {
    int r   = blockIdx.x;
    int tid = threadIdx.x;

    __shared__ __align__(16) float sA2[D_DIM * 32];       // [d][c dup pairs]
    __shared__ __align__(16) float sB2[D_DIM * 32];
    __shared__ __align__(16) float xs[2][DCHUNK * XROW];
    __shared__ int   smask[D_DIM];
    __shared__ float sbase[C_DIM];

    // ---- mask first (gather addresses) ----
    if (tid < D_DIM) smask[tid] = mask[r * D_DIM + tid];
    __syncthreads();

    const float* xTp = g_xT;
    int q    = tid & 127;                          // float4 index within a d-row
    int half = tid >> 7;                           // 0/1: which d-rows this thread fills
    uint32_t dst_off = (uint32_t)((q >> 2) * 20 + (q & 3) * 4) * 4u;  // bytes in row
    uint32_t xs_base[2] = { smem_u32(&xs[0][0]), smem_u32(&xs[1][0]) };

    // ---- chunk 0 gather in flight while we do the coefficient math ----
    #pragma unroll
    for (int s = half; s < DCHUNK; s += 2)
        cp_async16(xs_base[0] + (uint32_t)(s * XROW) * 4u + dst_off,
                   xTp + (size_t)smask[s] * B_DIM + q * 4);
    asm volatile("cp.async.commit_group;");

    // ---- stage loc/scale rows (coalesced) into xs[1] (free right now) ----
    float* sloc     = &xs[1][0];
    float* ssc      = &xs[1][784];
    float* scontrib = &xs[1][1568];     // [c][d]
    for (int i = tid; i < 784; i += 256) {
        sloc[i] = loc[r * 784 + i];
        ssc[i]  = scale[r * 784 + i];
    }
    __syncthreads();

    // ---- coefficients straight into smem tiles ----
    for (int i = tid; i < 784; i += 256) {
        int d = i >> 4;                 // i = d*16 + c
        int c = i & 15;
        int sl = c * D_DIM + d;         // source layout [c][d]
        float lc = sloc[sl];
        float sc = ssc[sl];
        float A, Bv, contrib;
        if (sc > 0.0f) {
            float inv = 1.0f / sc;
            float w = inv * inv;
            A = -0.5f * w;
            Bv = w * lc;
            contrib = -0.5f * w * lc * lc - __logf(sc) - HALF_LOG_2PI;
        } else {
            A = 0.0f; Bv = 0.0f; contrib = 0.0f;   // reference zeroes NaN logp
        }
        sA2[d * 32 + c * 2]     = A;
        sA2[d * 32 + c * 2 + 1] = A;
        sB2[d * 32 + c * 2]     = Bv;
        sB2[d * 32 + c * 2 + 1] = Bv;
        scontrib[sl] = contrib;
    }
    __syncthreads();

    // ---- base[c] reduction: 16 threads per c, shuffle within 16-lane groups ----
    {
        int c = tid >> 4;           // 0..15
        int l = tid & 15;
        float s = 0.0f;
        for (int d = l; d < D_DIM; d += 16) s += scontrib[c * D_DIM + d];
        s += __shfl_down_sync(0xffffffffu, s, 8, 16);
        s += __shfl_down_sync(0xffffffffu, s, 4, 16);
        s += __shfl_down_sync(0xffffffffu, s, 2, 16);
        s += __shfl_down_sync(0xffffffffu, s, 1, 16);
        if (l == 0) sbase[c] = s;
    }
    __syncthreads();    // staging reads done -> xs[1] free for chunk 1

    // ---- chunk 1 gather ----
    #pragma unroll
    for (int s = half; s < DCHUNK; s += 2)
        cp_async16(xs_base[1] + (uint32_t)(s * XROW) * 4u + dst_off,
                   xTp + (size_t)smask[DCHUNK + s] * B_DIM + q * 4);
    asm volatile("cp.async.commit_group;");

    int g = tid >> 3;    // 0..31 -> b segment (16 b's)
    int h = tid & 7;     // 0..7  -> c pair {2h, 2h+1}

    unsigned long long acc[8][2];
    #pragma unroll
    for (int p = 0; p < 8; ++p) { acc[p][0] = 0ull; acc[p][1] = 0ull; }

    for (int k = 0; k < NCHUNK; ++k) {
        if (k < NCHUNK - 1) asm volatile("cp.async.wait_group 1;");
        else                asm volatile("cp.async.wait_group 0;");
        __syncthreads();                     // buf[k&1] visible to all

        const float* xb = &xs[k & 1][g * 20];
        const float* Ab = sA2 + k * (DCHUNK * 32) + h * 4;
        const float* Bb = sB2 + k * (DCHUNK * 32) + h * 4;

        #pragma unroll
        for (int dd = 0; dd < DCHUNK; ++dd) {
            ulonglong2 xa = *reinterpret_cast<const ulonglong2*>(xb + dd * XROW);
            ulonglong2 xc = *reinterpret_cast<const ulonglong2*>(xb + dd * XROW + 4);
            ulonglong2 xe = *reinterpret_cast<const ulonglong2*>(xb + dd * XROW + 8);
            ulonglong2 xg = *reinterpret_cast<const ulonglong2*>(xb + dd * XROW + 12);
            ulonglong2 aa = *reinterpret_cast<const ulonglong2*>(Ab + dd * 32);
            ulonglong2 ba = *reinterpret_cast<const ulonglong2*>(Bb + dd * 32);
            unsigned long long x2[8] = {xa.x, xa.y, xc.x, xc.y, xe.x, xe.y, xg.x, xg.y};
            unsigned long long a2[2] = {aa.x, aa.y};
            unsigned long long b2[2] = {ba.x, ba.y};
            #pragma unroll
            for (int j = 0; j < 2; ++j)
                #pragma unroll
                for (int p = 0; p < 8; ++p) {
                    unsigned long long t = fma2(a2[j], x2[p], b2[j]);
                    acc[p][j] = fma2(x2[p], t, acc[p][j]);
                }
        }
        __syncthreads();                     // done reading buf[k&1]

        if (k + 2 < NCHUNK) {                // refill buf[k&1] with chunk k+2
            int d0 = (k + 2) * DCHUNK;
            #pragma unroll
            for (int s = half; s < DCHUNK; s += 2)
                cp_async16(xs_base[k & 1] + (uint32_t)(s * XROW) * 4u + dst_off,
                           xTp + (size_t)smask[d0 + s] * B_DIM + q * 4);
            asm volatile("cp.async.commit_group;");
        }
    }

    // ---- epilogue: unpack pairs, add base, store ----
    float bb0 = sbase[2 * h];
    float bb1 = sbase[2 * h + 1];
    int b0 = g * 16;

    #pragma unroll
    for (int p = 0; p < 8; ++p) {
        float lo0, hi0, lo1, hi1;
        unpack2(acc[p][0], lo0, hi0);
        unpack2(acc[p][1], lo1, hi1);
        size_t row = (size_t)(b0 + 2 * p) * (R_DIM * C_DIM) + r * C_DIM + 2 * h;
        float2 o0 = make_float2(lo0 + bb0, lo1 + bb1);
        float2 o1 = make_float2(hi0 + bb0, hi1 + bb1);
        *reinterpret_cast<float2*>(out + row) = o0;
        *reinterpret_cast<float2*>(out + row + (R_DIM * C_DIM)) = o1;
    }
}

// ---------------------------------------------------------------------------
extern "C" void kernel_launch(void* const* d_in, const int* in_sizes, int n_in,
                              void* d_out, int out_size) {
    const float* x     = (const float*)d_in[0];
    const int*   mask  = (const int*)d_in[1];
    const float* loc   = (const float*)d_in[2];
    const float* scale = (const float*)d_in[3];
    float* out = (float*)d_out;

    transpose_kernel<<<dim3((F_DIM + 31) / 32, B_DIM / 32), dim3(32, 8)>>>(x);
    main_kernel<<<R_DIM, 256>>>(loc, scale, mask, out);
}